// round 4
// baseline (speedup 1.0000x reference)
#include <cuda_runtime.h>

#define HDIM 64
#define NUM_GRAD_STEPS 4
#define INNER_LR 0.01f

typedef unsigned long long u64;

// ---- packed fp32x2 helpers (ptxas won't auto-fuse; PTX fma.rn.f32x2) ----
__device__ __forceinline__ u64 pack2(float lo, float hi) {
    u64 r; asm("mov.b64 %0, {%1,%2};" : "=l"(r) : "f"(lo), "f"(hi)); return r;
}
__device__ __forceinline__ float2 unpack2(u64 v) {
    float2 f; asm("mov.b64 {%0,%1}, %2;" : "=f"(f.x), "=f"(f.y) : "l"(v)); return f;
}
__device__ __forceinline__ u64 fma2(u64 a, u64 b, u64 c) {
    u64 d; asm("fma.rn.f32x2 %0, %1, %2, %3;" : "=l"(d) : "l"(a), "l"(b), "l"(c)); return d;
}

// 128 threads per block = one batch element. Thread t = (unit i = t>>1, half h = t&1).
// Thread holds HALF of W2 row i (cols 32h..32h+31) and HALF of W2 column i
// (rows 32h..32h+31). Halves of a unit are adjacent lanes -> shfl_xor(1) combine.
__global__ __launch_bounds__(128, 4) void ttt_kernel(
    const float* __restrict__ ts, const float* __restrict__ xs,
    const int*   __restrict__ mask,
    const float* __restrict__ W1g, const float* __restrict__ b1g,
    const float* __restrict__ W2g, const float* __restrict__ b2g,
    const float* __restrict__ W3g, const float* __restrict__ b3g,
    float* __restrict__ out, int T)
{
    __shared__ __align__(16) float h1s[HDIM];
    __shared__ __align__(16) float dz2s[HDIM];
    __shared__ float red[4];

    const int b    = blockIdx.x;
    const int tid  = threadIdx.x;       // 0..127
    const int i    = tid >> 1;          // hidden unit 0..63
    const int h    = tid & 1;           // half 0/1
    const int base = 32 * h;            // column/row offset of this half
    const int lane = tid & 31;
    const int warp = tid >> 5;

    // ---- load theta0 ----
    u64 w2row[16];   // w2row[m] = (W2[i][base+2m], W2[i][base+2m+1])
    u64 w2col[16];   // w2col[m] = (W2[base+2m][i], W2[base+2m+1][i])
    #pragma unroll
    for (int k = 0; k < 8; k++) {
        float4 v = *(const float4*)(W2g + i * HDIM + base + 4 * k);
        w2row[2 * k]     = pack2(v.x, v.y);
        w2row[2 * k + 1] = pack2(v.z, v.w);
    }
    #pragma unroll
    for (int m = 0; m < 16; m++) {
        float lo = W2g[(base + 2 * m) * HDIM + i];
        float hi = W2g[(base + 2 * m + 1) * HDIM + i];
        w2col[m] = pack2(lo, hi);
    }
    float w1a = W1g[2 * i];
    float w1b = W1g[2 * i + 1];
    float b1i = b1g[i];
    float b2i = b2g[i];
    float w3i = W3g[i];
    float b3  = b3g[0];

    const float* xrow = xs + (size_t)b * T;
    const int*   mrow = mask + (size_t)b * (T - 1);

    const float x0 = xrow[0];
    float x_hat = x0, x_prev = x0, t_prev = ts[0];
    if (tid == 0) out[(size_t)b * T] = x0;
    __syncthreads();

    // prefetched per-step scalars
    float t_c = ts[1], x_true = xrow[1];
    int   mcur = mrow[0];

    for (int s = 1; s < T; s++) {
        // prefetch next step (hide L2 latency behind this step's compute)
        float t_n = 0.f, x_n = 0.f; int m_n = 0;
        if (s + 1 < T) { t_n = ts[s + 1]; x_n = xrow[s + 1]; m_n = mrow[s]; }

        const float x_t = (mcur != 0) ? x_true : x_hat;

        #pragma unroll 1
        for (int g = 0; g < NUM_GRAD_STEPS; g++) {
            // ---- forward at (t_c, x_prev) ----
            const float h1 = tanhf(fmaf(w1a, t_c, fmaf(w1b, x_prev, b1i)));
            if (h == 0) h1s[i] = h1;
            __syncthreads();                                  // sync A

            u64 a0 = h ? 0ull : pack2(b2i, 0.f);
            u64 a1 = 0ull, a2 = 0ull, a3 = 0ull;
            #pragma unroll
            for (int k = 0; k < 4; k++) {
                float4 h0 = *(const float4*)(h1s + base + 8 * k);
                float4 h4 = *(const float4*)(h1s + base + 8 * k + 4);
                a0 = fma2(w2row[4 * k],     pack2(h0.x, h0.y), a0);
                a1 = fma2(w2row[4 * k + 1], pack2(h0.z, h0.w), a1);
                a2 = fma2(w2row[4 * k + 2], pack2(h4.x, h4.y), a2);
                a3 = fma2(w2row[4 * k + 3], pack2(h4.z, h4.w), a3);
            }
            float2 s0 = unpack2(a0), s1 = unpack2(a1), s2 = unpack2(a2), s3 = unpack2(a3);
            float z2p = ((s0.x + s0.y) + (s1.x + s1.y)) +
                        ((s2.x + s2.y) + (s3.x + s3.y));
            const float z2 = z2p + __shfl_xor_sync(0xffffffffu, z2p, 1);
            const float h2 = tanhf(z2);

            // pred = W3 . h2 + b3 : even-lane reduce (even xor offsets keep parity)
            float pp = (h == 0) ? w3i * h2 : 0.f;
            #pragma unroll
            for (int off = 2; off <= 16; off <<= 1)
                pp += __shfl_xor_sync(0xffffffffu, pp, off);
            if (lane == 0) red[warp] = pp;
            __syncthreads();                                  // sync B
            const float pred  = ((red[0] + red[1]) + (red[2] + red[3])) + b3;
            const float dpred = 2.0f * (pred - x_t);

            // ---- backward (all grads at OLD theta) ----
            const float dz2 = dpred * w3i * (1.0f - h2 * h2);  // old W3
            if (h == 0) dz2s[i] = dz2;
            w3i = fmaf(-INNER_LR * dpred, h2, w3i);
            b3  = fmaf(-INNER_LR, dpred, b3);
            b2i = fmaf(-INNER_LR, dz2, b2i);

            // row update: W2[i][base+k] -= lr*dz2_i*h1[base+k]
            const float amr = -INNER_LR * dz2;
            const u64 amrow = pack2(amr, amr);
            #pragma unroll
            for (int k = 0; k < 4; k++) {
                float4 h0 = *(const float4*)(h1s + base + 8 * k);
                float4 h4 = *(const float4*)(h1s + base + 8 * k + 4);
                w2row[4 * k]     = fma2(amrow, pack2(h0.x, h0.y), w2row[4 * k]);
                w2row[4 * k + 1] = fma2(amrow, pack2(h0.z, h0.w), w2row[4 * k + 1]);
                w2row[4 * k + 2] = fma2(amrow, pack2(h4.x, h4.y), w2row[4 * k + 2]);
                w2row[4 * k + 3] = fma2(amrow, pack2(h4.z, h4.w), w2row[4 * k + 3]);
            }
            __syncthreads();                                  // sync C

            // fused column pass (half): dh1 += W2_old[j][i]*dz2[j]; update col copy
            const float amc = -INNER_LR * h1;
            const u64 amcol = pack2(amc, amc);
            u64 d0 = 0ull, d1 = 0ull, d2 = 0ull, d3 = 0ull;
            #pragma unroll
            for (int j = 0; j < 4; j++) {
                float4 v0 = *(const float4*)(dz2s + base + 8 * j);
                float4 v4 = *(const float4*)(dz2s + base + 8 * j + 4);
                u64 p0 = pack2(v0.x, v0.y), p1 = pack2(v0.z, v0.w);
                u64 p2 = pack2(v4.x, v4.y), p3 = pack2(v4.z, v4.w);
                d0 = fma2(w2col[4 * j],     p0, d0);
                d1 = fma2(w2col[4 * j + 1], p1, d1);
                d2 = fma2(w2col[4 * j + 2], p2, d2);
                d3 = fma2(w2col[4 * j + 3], p3, d3);
                w2col[4 * j]     = fma2(amcol, p0, w2col[4 * j]);
                w2col[4 * j + 1] = fma2(amcol, p1, w2col[4 * j + 1]);
                w2col[4 * j + 2] = fma2(amcol, p2, w2col[4 * j + 2]);
                w2col[4 * j + 3] = fma2(amcol, p3, w2col[4 * j + 3]);
            }
            float2 e0 = unpack2(d0), e1 = unpack2(d1), e2 = unpack2(d2), e3 = unpack2(d3);
            float dh1p = ((e0.x + e0.y) + (e1.x + e1.y)) +
                         ((e2.x + e2.y) + (e3.x + e3.y));
            const float dh1 = dh1p + __shfl_xor_sync(0xffffffffu, dh1p, 1);
            const float dz1 = dh1 * (1.0f - h1 * h1);
            w1a = fmaf(-INNER_LR * dz1, t_c,    w1a);
            w1b = fmaf(-INNER_LR * dz1, x_prev, w1b);
            b1i = fmaf(-INNER_LR, dz1, b1i);
        }

        // ---- final forward with updated theta at (t_c + dt, x_true) ----
        const float tin = t_c + (t_c - t_prev);
        const float hf = tanhf(fmaf(w1a, tin, fmaf(w1b, x_true, b1i)));
        if (h == 0) h1s[i] = hf;          // after sync C: no race
        __syncthreads();

        u64 a0 = h ? 0ull : pack2(b2i, 0.f);
        u64 a1 = 0ull, a2 = 0ull, a3 = 0ull;
        #pragma unroll
        for (int k = 0; k < 4; k++) {
            float4 h0 = *(const float4*)(h1s + base + 8 * k);
            float4 h4 = *(const float4*)(h1s + base + 8 * k + 4);
            a0 = fma2(w2row[4 * k],     pack2(h0.x, h0.y), a0);
            a1 = fma2(w2row[4 * k + 1], pack2(h0.z, h0.w), a1);
            a2 = fma2(w2row[4 * k + 2], pack2(h4.x, h4.y), a2);
            a3 = fma2(w2row[4 * k + 3], pack2(h4.z, h4.w), a3);
        }
        float2 s0 = unpack2(a0), s1 = unpack2(a1), s2 = unpack2(a2), s3 = unpack2(a3);
        float z2p = ((s0.x + s0.y) + (s1.x + s1.y)) +
                    ((s2.x + s2.y) + (s3.x + s3.y));
        const float z2 = z2p + __shfl_xor_sync(0xffffffffu, z2p, 1);
        const float h2 = tanhf(z2);
        float pp = (h == 0) ? w3i * h2 : 0.f;
        #pragma unroll
        for (int off = 2; off <= 16; off <<= 1)
            pp += __shfl_xor_sync(0xffffffffu, pp, off);
        if (lane == 0) red[warp] = pp;
        __syncthreads();
        x_hat = ((red[0] + red[1]) + (red[2] + red[3])) + b3;

        if (tid == 0) out[(size_t)b * T + s] = x_hat;
        x_prev = x_true;
        t_prev = t_c;
        t_c = t_n; x_true = x_n; mcur = m_n;
    }
}

extern "C" void kernel_launch(void* const* d_in, const int* in_sizes, int n_in,
                              void* d_out, int out_size) {
    const float* ts   = (const float*)d_in[0];
    const float* xs   = (const float*)d_in[1];
    const int*   mask = (const int*)  d_in[2];
    const float* W1   = (const float*)d_in[3];
    const float* b1   = (const float*)d_in[4];
    const float* W2   = (const float*)d_in[5];
    const float* b2   = (const float*)d_in[6];
    const float* W3   = (const float*)d_in[7];
    const float* b3   = (const float*)d_in[8];

    const int T = in_sizes[0];
    const int B = in_sizes[1] / T;

    ttt_kernel<<<B, 128>>>(ts, xs, mask, W1, b1, W2, b2, W3, b3,
                           (float*)d_out, T);
}

// round 6
// speedup vs baseline: 1.1925x; 1.1925x over previous
#include <cuda_runtime.h>

#define HDIM 64
#define NUM_GRAD_STEPS 4
#define INNER_LR 0.01f

typedef unsigned long long u64;

// ---- packed fp32x2 helpers (ptxas won't auto-fuse; PTX fma.rn.f32x2) ----
__device__ __forceinline__ u64 pack2(float lo, float hi) {
    u64 r; asm("mov.b64 %0, {%1,%2};" : "=l"(r) : "f"(lo), "f"(hi)); return r;
}
__device__ __forceinline__ float2 unpack2(u64 v) {
    float2 f; asm("mov.b64 {%0,%1}, %2;" : "=f"(f.x), "=f"(f.y) : "l"(v)); return f;
}
__device__ __forceinline__ u64 fma2(u64 a, u64 b, u64 c) {
    u64 d; asm("fma.rn.f32x2 %0, %1, %2, %3;" : "=l"(d) : "l"(a), "l"(b), "l"(c)); return d;
}
// warp f32 sum: butterfly shfl (redux.sync.add.f32 unsupported on sm_103)
__device__ __forceinline__ float warp_sum(float v) {
    #pragma unroll
    for (int off = 16; off; off >>= 1)
        v += __shfl_xor_sync(0xffffffffu, v, off);
    return v;
}

// One block (64 threads) per batch element. Thread i owns hidden unit i.
// W2 lives ONLY in registers: w2row[32] = row i (pairs), w2col[32] = col i (pairs).
// Shared memory: ping-pong h1 broadcast, u = w3*(1-h2^2) broadcast, 2 warp partials.
__global__ __launch_bounds__(64, 6) void ttt_kernel(
    const float* __restrict__ ts, const float* __restrict__ xs,
    const int*   __restrict__ mask,
    const float* __restrict__ W1g, const float* __restrict__ b1g,
    const float* __restrict__ W2g, const float* __restrict__ b2g,
    const float* __restrict__ W3g, const float* __restrict__ b3g,
    float* __restrict__ out, int T)
{
    __shared__ __align__(16) float h1buf[2][HDIM];
    __shared__ __align__(16) float us[HDIM];
    __shared__ float red[2];

    const int b    = blockIdx.x;
    const int i    = threadIdx.x;       // 0..63
    const int lane = i & 31;
    const int warp = i >> 5;

    // ---- load theta0 ----
    u64 w2row[32];   // (W2[i][2m], W2[i][2m+1])
    u64 w2col[32];   // (W2[2m][i], W2[2m+1][i])
    #pragma unroll
    for (int k = 0; k < 16; k++) {
        float4 v = *(const float4*)(W2g + i * HDIM + 4 * k);
        w2row[2 * k]     = pack2(v.x, v.y);
        w2row[2 * k + 1] = pack2(v.z, v.w);
    }
    #pragma unroll
    for (int m = 0; m < 32; m++) {
        float lo = W2g[(2 * m) * HDIM + i];
        float hi = W2g[(2 * m + 1) * HDIM + i];
        w2col[m] = pack2(lo, hi);
    }
    float w1a = W1g[2 * i];
    float w1b = W1g[2 * i + 1];
    float b1i = b1g[i];
    float b2i = b2g[i];
    float w3i = W3g[i];
    float b3  = b3g[0];

    const float* xrow = xs + (size_t)b * T;
    const int*   mrow = mask + (size_t)b * (T - 1);

    const float x0 = xrow[0];
    float x_hat = x0, x_prev = x0, t_prev = ts[0];
    if (i == 0) out[(size_t)b * T] = x0;
    __syncthreads();

    float t_c = ts[1], x_true = xrow[1];
    int   mcur = mrow[0];

    for (int s = 1; s < T; s++) {
        float t_n = 0.f, x_n = 0.f; int m_n = 0;
        if (s + 1 < T) { t_n = ts[s + 1]; x_n = xrow[s + 1]; m_n = mrow[s]; }

        const float x_t = (mcur != 0) ? x_true : x_hat;

        #pragma unroll 1
        for (int g = 0; g < NUM_GRAD_STEPS; g++) {
            float* h1b = h1buf[g & 1];
            // ---- forward at (t_c, x_prev) ----
            const float h1 = tanhf(fmaf(w1a, t_c, fmaf(w1b, x_prev, b1i)));
            h1b[i] = h1;
            __syncthreads();                                  // bar 1

            const u64* hp = (const u64*)h1b;
            u64 a0 = 0ull, a1 = 0ull, a2 = 0ull, a3 = 0ull;
            #pragma unroll
            for (int k = 0; k < 8; k++) {
                a0 = fma2(w2row[4 * k],     hp[4 * k],     a0);
                a1 = fma2(w2row[4 * k + 1], hp[4 * k + 1], a1);
                a2 = fma2(w2row[4 * k + 2], hp[4 * k + 2], a2);
                a3 = fma2(w2row[4 * k + 3], hp[4 * k + 3], a3);
            }
            float2 s0 = unpack2(a0), s1 = unpack2(a1), s2 = unpack2(a2), s3 = unpack2(a3);
            const float z2 = b2i + (((s0.x + s0.y) + (s1.x + s1.y)) +
                                    ((s2.x + s2.y) + (s3.x + s3.y)));
            const float h2 = tanhf(z2);

            // warp-partial of pred and the u-broadcast share ONE barrier
            const float u  = w3i * (1.0f - h2 * h2);
            us[i] = u;                      // store first: overlaps shfl chain
            const float pw = warp_sum(w3i * h2);
            if (lane == 0) red[warp] = pw;
            __syncthreads();                                  // bar 2

            const float pred  = (red[0] + red[1]) + b3;
            const float dpred = 2.0f * (pred - x_t);
            const float dz2   = dpred * u;                    // own dz2 (old W3)

            w3i = fmaf(-INNER_LR * dpred, h2, w3i);
            b3  = fmaf(-INNER_LR, dpred, b3);
            b2i = fmaf(-INNER_LR, dz2, b2i);

            // row update: W2[i][k] -= lr*dz2_i*h1[k]
            const float amr = -INNER_LR * dz2;
            const u64 amrow = pack2(amr, amr);
            #pragma unroll
            for (int k = 0; k < 8; k++) {
                w2row[4 * k]     = fma2(amrow, hp[4 * k],     w2row[4 * k]);
                w2row[4 * k + 1] = fma2(amrow, hp[4 * k + 1], w2row[4 * k + 1]);
                w2row[4 * k + 2] = fma2(amrow, hp[4 * k + 2], w2row[4 * k + 2]);
                w2row[4 * k + 3] = fma2(amrow, hp[4 * k + 3], w2row[4 * k + 3]);
            }

            // fused column pass: dh1 = dpred * sum_j W2old[j][i]*u[j];
            // W2[j][i] -= lr*(dpred*u[j])*h1_i
            const float amc = -INNER_LR * dpred * h1;
            const u64 amcol = pack2(amc, amc);
            const u64* up = (const u64*)us;
            u64 d0 = 0ull, d1 = 0ull, d2 = 0ull, d3 = 0ull;
            #pragma unroll
            for (int j = 0; j < 8; j++) {
                u64 p0 = up[4 * j],     p1 = up[4 * j + 1];
                u64 p2 = up[4 * j + 2], p3 = up[4 * j + 3];
                d0 = fma2(w2col[4 * j],     p0, d0);
                d1 = fma2(w2col[4 * j + 1], p1, d1);
                d2 = fma2(w2col[4 * j + 2], p2, d2);
                d3 = fma2(w2col[4 * j + 3], p3, d3);
                w2col[4 * j]     = fma2(amcol, p0, w2col[4 * j]);
                w2col[4 * j + 1] = fma2(amcol, p1, w2col[4 * j + 1]);
                w2col[4 * j + 2] = fma2(amcol, p2, w2col[4 * j + 2]);
                w2col[4 * j + 3] = fma2(amcol, p3, w2col[4 * j + 3]);
            }
            float2 e0 = unpack2(d0), e1 = unpack2(d1), e2 = unpack2(d2), e3 = unpack2(d3);
            const float dh1 = dpred * (((e0.x + e0.y) + (e1.x + e1.y)) +
                                       ((e2.x + e2.y) + (e3.x + e3.y)));
            const float dz1 = dh1 * (1.0f - h1 * h1);
            w1a = fmaf(-INNER_LR * dz1, t_c,    w1a);
            w1b = fmaf(-INNER_LR * dz1, x_prev, w1b);
            b1i = fmaf(-INNER_LR, dz1, b1i);
        }

        // ---- final forward with updated theta at (t_c + dt, x_true) ----
        // buffer 0: last readers finished before bar1 of g=3 -> ordered
        const float tin = t_c + (t_c - t_prev);
        const float hf = tanhf(fmaf(w1a, tin, fmaf(w1b, x_true, b1i)));
        h1buf[0][i] = hf;
        __syncthreads();                                      // bar F1

        const u64* hp = (const u64*)h1buf[0];
        u64 a0 = 0ull, a1 = 0ull, a2 = 0ull, a3 = 0ull;
        #pragma unroll
        for (int k = 0; k < 8; k++) {
            a0 = fma2(w2row[4 * k],     hp[4 * k],     a0);
            a1 = fma2(w2row[4 * k + 1], hp[4 * k + 1], a1);
            a2 = fma2(w2row[4 * k + 2], hp[4 * k + 2], a2);
            a3 = fma2(w2row[4 * k + 3], hp[4 * k + 3], a3);
        }
        float2 s0 = unpack2(a0), s1 = unpack2(a1), s2 = unpack2(a2), s3 = unpack2(a3);
        const float z2 = b2i + (((s0.x + s0.y) + (s1.x + s1.y)) +
                                ((s2.x + s2.y) + (s3.x + s3.y)));
        const float h2 = tanhf(z2);
        const float pw = warp_sum(w3i * h2);
        if (lane == 0) red[warp] = pw;
        __syncthreads();                                      // bar F2
        x_hat = (red[0] + red[1]) + b3;

        if (i == 0) out[(size_t)b * T + s] = x_hat;
        x_prev = x_true;
        t_prev = t_c;
        t_c = t_n; x_true = x_n; mcur = m_n;
    }
}

extern "C" void kernel_launch(void* const* d_in, const int* in_sizes, int n_in,
                              void* d_out, int out_size) {
    const float* ts   = (const float*)d_in[0];
    const float* xs   = (const float*)d_in[1];
    const int*   mask = (const int*)  d_in[2];
    const float* W1   = (const float*)d_in[3];
    const float* b1   = (const float*)d_in[4];
    const float* W2   = (const float*)d_in[5];
    const float* b2   = (const float*)d_in[6];
    const float* W3   = (const float*)d_in[7];
    const float* b3   = (const float*)d_in[8];

    const int T = in_sizes[0];
    const int B = in_sizes[1] / T;

    ttt_kernel<<<B, HDIM>>>(ts, xs, mask, W1, b1, W2, b2, W3, b3,
                            (float*)d_out, T);
}